// round 8
// baseline (speedup 1.0000x reference)
#include <cuda_runtime.h>
#include <cstdint>

typedef unsigned long long ull;

#define NB 128
#define NT 4096
#define K1_NTH 256
#define NCHUNK 4            // CTAs per batch (all co-resident: 512 <= 148*4)
#define TOKC 1024           // tokens per CTA

__device__ float g_scratch[NB * NCHUNK * 18];   // [cta][lmax, sum, ctx16]
__device__ int   g_cnt1[NB];                    // arrival counters (zero-init)
__device__ int   g_cnt2[NB];                    // completion counters

__device__ __forceinline__ float ex2f_(float x) {
    float y; asm("ex2.approx.f32 %0, %1;" : "=f"(y) : "f"(x)); return y;
}
__device__ __forceinline__ float rcpf_(float x) {
    float y; asm("rcp.approx.f32 %0, %1;" : "=f"(y) : "f"(x)); return y;
}
__device__ __forceinline__ float tanhf_(float x) {
    float y; asm("tanh.approx.f32 %0, %1;" : "=f"(y) : "f"(x)); return y;
}
__device__ __forceinline__ void pfma(ull& d, ull a, ull b) {
    asm("fma.rn.f32x2 %0, %1, %2, %0;" : "+l"(d) : "l"(a), "l"(b));
}
__device__ __forceinline__ ull pack2(float a, float b) {
    ull p; asm("mov.b64 %0, {%1, %2};" : "=l"(p) : "f"(a), "f"(b)); return p;
}
__device__ __forceinline__ float2 unpack2(ull p) {
    float2 r; asm("mov.b64 {%0, %1}, %2;" : "=f"(r.x), "=f"(r.y) : "l"(p)); return r;
}
__device__ __forceinline__ void red_release_add(int* p, int v) {
    asm volatile("red.release.gpu.global.add.s32 [%0], %1;" :: "l"(p), "r"(v) : "memory");
}
__device__ __forceinline__ int ld_acquire(const int* p) {
    int v; asm volatile("ld.acquire.gpu.global.s32 %0, [%1];" : "=r"(v) : "l"(p) : "memory");
    return v;
}

__global__ void __launch_bounds__(K1_NTH, 4)
attn_fused(const float* __restrict__ query,   // [B,1,16]
           const float* __restrict__ key,     // [B,T,16]
           const float* __restrict__ value,   // [B,T,16]
           const float* __restrict__ W1,      // [32,16]
           const float* __restrict__ W2,      // [32,16]
           const float* __restrict__ bias,    // scalar
           const float* __restrict__ v_w,     // [1,32]
           const float* __restrict__ v_b,     // [1]
           float* __restrict__ out_ctx,       // [B,16]
           float* __restrict__ out_attn)      // [B,T]
{
    const int cta   = blockIdx.x;
    const int b     = cta >> 2;
    const int chunk = cta & 3;
    const int base  = chunk * TOKC;
    const int tid   = threadIdx.x;
    const int lane  = tid & 31;
    const int wid   = tid >> 5;

    __shared__ ull        sW2p[32 * 8];
    __shared__ ulonglong2 scv[32];        // .x = (qproj_w + bias, 0), .y lo = v_w[w]
    __shared__ float      sred[8 * 17];
    __shared__ float      sbc[1];         // local max broadcast
    __shared__ float      sfac[4];        // combine factors

    if (tid < 128) {
        float4 wr = reinterpret_cast<const float4*>(W2)[tid];
        sW2p[tid * 2 + 0] = pack2(wr.x, wr.y);
        sW2p[tid * 2 + 1] = pack2(wr.z, wr.w);
    }
    if (tid >= 128 && tid < 160) {
        const int w = tid - 128;
        float acc = *bias;
        #pragma unroll
        for (int d = 0; d < 16; d++)
            acc = fmaf(query[b * 16 + d], W1[w * 16 + d], acc);
        scv[w].x = pack2(acc, 0.0f);
        scv[w].y = pack2(v_w[w], 0.0f);
    }
    __syncthreads();

    const float vb = *v_b;

    // ---------- Phase A: scores for 4 tokens (2 per pass) ----------
    float s[4];
    #pragma unroll
    for (int jp = 0; jp < 2; jp++) {
        const int t0 = base + tid + (2 * jp + 0) * K1_NTH;
        const int t1 = base + tid + (2 * jp + 1) * K1_NTH;
        const ulonglong2* kp0 =
            reinterpret_cast<const ulonglong2*>(key + ((size_t)b * NT + t0) * 16);
        const ulonglong2* kp1 =
            reinterpret_cast<const ulonglong2*>(key + ((size_t)b * NT + t1) * 16);
        ull ka[8], kb[8];
        #pragma unroll
        for (int i = 0; i < 4; i++) {
            ulonglong2 va = kp0[i]; ka[2*i] = va.x; ka[2*i+1] = va.y;
            ulonglong2 vb_ = kp1[i]; kb[2*i] = vb_.x; kb[2*i+1] = vb_.y;
        }

        float a0 = vb, a1 = vb;
        #pragma unroll 4
        for (int w = 0; w < 32; w++) {
            const ulonglong2 cc = scv[w];
            ull acc0 = cc.x;
            ull acc1 = cc.x;
            const float vw = unpack2(cc.y).x;
            const ulonglong2* wr =
                reinterpret_cast<const ulonglong2*>(&sW2p[w * 8]);
            ulonglong2 wv = wr[0];
            pfma(acc0, ka[0], wv.x); pfma(acc1, kb[0], wv.x);
            pfma(acc0, ka[1], wv.y); pfma(acc1, kb[1], wv.y);
            wv = wr[1];
            pfma(acc0, ka[2], wv.x); pfma(acc1, kb[2], wv.x);
            pfma(acc0, ka[3], wv.y); pfma(acc1, kb[3], wv.y);
            wv = wr[2];
            pfma(acc0, ka[4], wv.x); pfma(acc1, kb[4], wv.x);
            pfma(acc0, ka[5], wv.y); pfma(acc1, kb[5], wv.y);
            wv = wr[3];
            pfma(acc0, ka[6], wv.x); pfma(acc1, kb[6], wv.x);
            pfma(acc0, ka[7], wv.y); pfma(acc1, kb[7], wv.y);

            const float2 h0 = unpack2(acc0);
            const float2 h1 = unpack2(acc1);
            const float t0h = tanhf_(h0.x + h0.y);
            const float t1h = tanhf_(h1.x + h1.y);
            a0 = fmaf(vw, t0h, a0);
            a1 = fmaf(vw, t1h, a1);
        }
        s[2 * jp + 0] = a0;
        s[2 * jp + 1] = a1;
    }

    // ---------- CTA-local max (8 warps) ----------
    float m = fmaxf(fmaxf(s[0], s[1]), fmaxf(s[2], s[3]));
    #pragma unroll
    for (int o = 16; o > 0; o >>= 1)
        m = fmaxf(m, __shfl_xor_sync(0xffffffffu, m, o));
    if (lane == 0) sred[wid] = m;
    __syncthreads();
    if (wid == 0) {
        float mm = (lane < 8) ? sred[lane] : -3.4e38f;
        #pragma unroll
        for (int o = 16; o > 0; o >>= 1)
            mm = fmaxf(mm, __shfl_xor_sync(0xffffffffu, mm, o));
        if (lane == 0) sbc[0] = mm;
    }
    __syncthreads();
    const float lmax  = sbc[0];
    const float L     = 1.4426950408889634f;
    const float negmL = -lmax * L;

    // ---------- Phase B: e (kept in regs) + weighted value accumulation ----------
    float e_[4];
    float csum = 0.0f;
    ull cv[8];
    #pragma unroll
    for (int i = 0; i < 8; i++) cv[i] = 0ull;

    #pragma unroll
    for (int j = 0; j < 4; j++) {
        const int t = base + tid + j * K1_NTH;
        const float e = ex2f_(fmaf(s[j], L, negmL));
        e_[j] = e;
        csum += e;
        const ull ee = pack2(e, e);
        const ulonglong2* vp =
            reinterpret_cast<const ulonglong2*>(value + ((size_t)b * NT + t) * 16);
        #pragma unroll
        for (int i = 0; i < 4; i++) {
            ulonglong2 vv = vp[i];
            pfma(cv[2*i],   ee, vv.x);
            pfma(cv[2*i+1], ee, vv.y);
        }
    }

    float cvf[16];
    #pragma unroll
    for (int i = 0; i < 8; i++) {
        float2 u = unpack2(cv[i]);
        cvf[2*i] = u.x; cvf[2*i+1] = u.y;
    }

    // ---------- Deterministic 17-value reduction over 8 warps ----------
    #pragma unroll
    for (int o = 16; o > 0; o >>= 1) {
        csum += __shfl_xor_sync(0xffffffffu, csum, o);
        #pragma unroll
        for (int i = 0; i < 16; i++)
            cvf[i] += __shfl_xor_sync(0xffffffffu, cvf[i], o);
    }
    if (lane == 0) {
        sred[wid * 17] = csum;
        #pragma unroll
        for (int i = 0; i < 16; i++) sred[wid * 17 + 1 + i] = cvf[i];
    }
    __syncthreads();
    if (tid < 17) {
        float a = sred[tid];
        #pragma unroll
        for (int w = 1; w < 8; w++) a += sred[w * 17 + tid];
        g_scratch[cta * 18 + 1 + tid] = a;      // sum, ctx[16]
    }
    if (tid == 17) g_scratch[cta * 18] = lmax;
    __syncthreads();   // all scratch writes done before the release-add

    // ---------- Cross-CTA combine: arrive + spin (all 512 CTAs co-resident) ----------
    if (tid == 0) {
        red_release_add(&g_cnt1[b], 1);
        while (ld_acquire(&g_cnt1[b]) < NCHUNK) __nanosleep(32);
    }
    __syncthreads();

    // All 4 partials visible; compute combine factors (one thread, broadcast)
    if (tid == 0) {
        const float* gs = g_scratch + b * (NCHUNK * 18);
        const float l0 = gs[0], l1 = gs[18], l2 = gs[36], l3 = gs[54];
        const float gmax = fmaxf(fmaxf(l0, l1), fmaxf(l2, l3));
        const float c0 = ex2f_((l0 - gmax) * L);
        const float c1 = ex2f_((l1 - gmax) * L);
        const float c2 = ex2f_((l2 - gmax) * L);
        const float c3 = ex2f_((l3 - gmax) * L);
        const float total = gs[1]*c0 + gs[19]*c1 + gs[37]*c2 + gs[55]*c3;
        const float inv = rcpf_(total);
        sfac[0] = c0 * inv; sfac[1] = c1 * inv;
        sfac[2] = c2 * inv; sfac[3] = c3 * inv;
    }
    __syncthreads();

    // chunk 0 writes context
    if (chunk == 0 && tid < 16) {
        const float* gs = g_scratch + b * (NCHUNK * 18);
        out_ctx[b * 16 + tid] = gs[2 + tid]  * sfac[0] + gs[20 + tid] * sfac[1]
                              + gs[38 + tid] * sfac[2] + gs[56 + tid] * sfac[3];
    }

    // write normalized attn straight from registers (single store)
    const float sc = sfac[chunk];
    #pragma unroll
    for (int j = 0; j < 4; j++)
        out_attn[(size_t)b * NT + base + tid + j * K1_NTH] = e_[j] * sc;

    // ---------- Counter reset for graph replay (last CTA of batch) ----------
    __syncthreads();
    if (tid == 0) {
        // cnt2 increments only after the spin passed in every CTA, so the
        // last arriver can safely zero both counters for the next launch.
        if (atomicAdd(&g_cnt2[b], 1) == NCHUNK - 1) {
            g_cnt1[b] = 0;
            __threadfence();
            g_cnt2[b] = 0;
        }
    }
}

extern "C" void kernel_launch(void* const* d_in, const int* in_sizes, int n_in,
                              void* d_out, int out_size) {
    const float* query = (const float*)d_in[0];
    const float* key   = (const float*)d_in[1];
    const float* value = (const float*)d_in[2];
    const float* W1    = (const float*)d_in[3];
    const float* W2    = (const float*)d_in[4];
    const float* bias  = (const float*)d_in[5];
    const float* v_w   = (const float*)d_in[6];
    const float* v_b   = (const float*)d_in[7];

    float* out_ctx  = (float*)d_out;            // [B,1,16]
    float* out_attn = (float*)d_out + NB * 16;  // [B,T]

    attn_fused<<<NB * NCHUNK, K1_NTH>>>(query, key, value, W1, W2,
                                        bias, v_w, v_b, out_ctx, out_attn);
}

// round 9
// speedup vs baseline: 1.0690x; 1.0690x over previous
#include <cuda_runtime.h>
#include <cstdint>

typedef unsigned long long ull;

#define NB 128
#define NT 4096
#define K1_NTH 128
#define NCHUNK 8            // CTAs per batch (grid 1024 <= 148*8 resident slots)
#define TOKC 512            // tokens per CTA

__device__ float g_scratch[NB * NCHUNK * 18];   // [cta][lmax, sum, ctx16]
__device__ int   g_cnt1[NB];                    // arrival counters (zero-init)
__device__ int   g_cnt2[NB];                    // completion counters

__device__ __forceinline__ float ex2f_(float x) {
    float y; asm("ex2.approx.f32 %0, %1;" : "=f"(y) : "f"(x)); return y;
}
__device__ __forceinline__ float rcpf_(float x) {
    float y; asm("rcp.approx.f32 %0, %1;" : "=f"(y) : "f"(x)); return y;
}
__device__ __forceinline__ float tanhf_(float x) {
    float y; asm("tanh.approx.f32 %0, %1;" : "=f"(y) : "f"(x)); return y;
}
__device__ __forceinline__ void pfma(ull& d, ull a, ull b) {
    asm("fma.rn.f32x2 %0, %1, %2, %0;" : "+l"(d) : "l"(a), "l"(b));
}
__device__ __forceinline__ ull pack2(float a, float b) {
    ull p; asm("mov.b64 %0, {%1, %2};" : "=l"(p) : "f"(a), "f"(b)); return p;
}
__device__ __forceinline__ float2 unpack2(ull p) {
    float2 r; asm("mov.b64 {%0, %1}, %2;" : "=f"(r.x), "=f"(r.y) : "l"(p)); return r;
}
__device__ __forceinline__ void red_release_add(int* p, int v) {
    asm volatile("red.release.gpu.global.add.s32 [%0], %1;" :: "l"(p), "r"(v) : "memory");
}
__device__ __forceinline__ int ld_acquire(const int* p) {
    int v; asm volatile("ld.acquire.gpu.global.s32 %0, [%1];" : "=r"(v) : "l"(p) : "memory");
    return v;
}

__global__ void __launch_bounds__(K1_NTH, 8)
attn_fused(const float* __restrict__ query,   // [B,1,16]
           const float* __restrict__ key,     // [B,T,16]
           const float* __restrict__ value,   // [B,T,16]
           const float* __restrict__ W1,      // [32,16]
           const float* __restrict__ W2,      // [32,16]
           const float* __restrict__ bias,    // scalar
           const float* __restrict__ v_w,     // [1,32]
           const float* __restrict__ v_b,     // [1]
           float* __restrict__ out_ctx,       // [B,16]
           float* __restrict__ out_attn)      // [B,T]
{
    const int cta   = blockIdx.x;
    const int b     = cta >> 3;
    const int chunk = cta & 7;
    const int base  = chunk * TOKC;
    const int tid   = threadIdx.x;
    const int lane  = tid & 31;
    const int wid   = tid >> 5;

    __shared__ ull        sW2p[32 * 8];
    __shared__ ulonglong2 scv[32];        // .x = (qproj_w + bias, 0), .y lo = v_w[w]
    __shared__ float      sred[4 * 17];
    __shared__ float      sbc[1];         // local max broadcast
    __shared__ float      sfac[NCHUNK];   // combine factors

    if (tid < 128) {
        float4 wr = reinterpret_cast<const float4*>(W2)[tid];
        sW2p[tid * 2 + 0] = pack2(wr.x, wr.y);
        sW2p[tid * 2 + 1] = pack2(wr.z, wr.w);
    }
    if (tid < 32) {
        const int w = tid;
        float acc = *bias;
        #pragma unroll
        for (int d = 0; d < 16; d++)
            acc = fmaf(query[b * 16 + d], W1[w * 16 + d], acc);
        scv[w].x = pack2(acc, 0.0f);
        scv[w].y = pack2(v_w[w], 0.0f);
    }
    __syncthreads();

    const float vb = *v_b;

    // ---------- Phase A: scores for 4 tokens (2 per pass) ----------
    float s[4];
    #pragma unroll
    for (int jp = 0; jp < 2; jp++) {
        const int t0 = base + tid + (2 * jp + 0) * K1_NTH;
        const int t1 = base + tid + (2 * jp + 1) * K1_NTH;
        const ulonglong2* kp0 =
            reinterpret_cast<const ulonglong2*>(key + ((size_t)b * NT + t0) * 16);
        const ulonglong2* kp1 =
            reinterpret_cast<const ulonglong2*>(key + ((size_t)b * NT + t1) * 16);
        ull ka[8], kb[8];
        #pragma unroll
        for (int i = 0; i < 4; i++) {
            ulonglong2 va = kp0[i]; ka[2*i] = va.x; ka[2*i+1] = va.y;
            ulonglong2 vb_ = kp1[i]; kb[2*i] = vb_.x; kb[2*i+1] = vb_.y;
        }

        float a0 = vb, a1 = vb;
        #pragma unroll 4
        for (int w = 0; w < 32; w++) {
            const ulonglong2 cc = scv[w];
            ull acc0 = cc.x;
            ull acc1 = cc.x;
            const float vw = unpack2(cc.y).x;
            const ulonglong2* wr =
                reinterpret_cast<const ulonglong2*>(&sW2p[w * 8]);
            ulonglong2 wv = wr[0];
            pfma(acc0, ka[0], wv.x); pfma(acc1, kb[0], wv.x);
            pfma(acc0, ka[1], wv.y); pfma(acc1, kb[1], wv.y);
            wv = wr[1];
            pfma(acc0, ka[2], wv.x); pfma(acc1, kb[2], wv.x);
            pfma(acc0, ka[3], wv.y); pfma(acc1, kb[3], wv.y);
            wv = wr[2];
            pfma(acc0, ka[4], wv.x); pfma(acc1, kb[4], wv.x);
            pfma(acc0, ka[5], wv.y); pfma(acc1, kb[5], wv.y);
            wv = wr[3];
            pfma(acc0, ka[6], wv.x); pfma(acc1, kb[6], wv.x);
            pfma(acc0, ka[7], wv.y); pfma(acc1, kb[7], wv.y);

            const float2 h0 = unpack2(acc0);
            const float2 h1 = unpack2(acc1);
            const float t0h = tanhf_(h0.x + h0.y);
            const float t1h = tanhf_(h1.x + h1.y);
            a0 = fmaf(vw, t0h, a0);
            a1 = fmaf(vw, t1h, a1);
        }
        s[2 * jp + 0] = a0;
        s[2 * jp + 1] = a1;
    }

    // ---------- CTA-local max (4 warps) ----------
    float m = fmaxf(fmaxf(s[0], s[1]), fmaxf(s[2], s[3]));
    #pragma unroll
    for (int o = 16; o > 0; o >>= 1)
        m = fmaxf(m, __shfl_xor_sync(0xffffffffu, m, o));
    if (lane == 0) sred[wid] = m;
    __syncthreads();
    if (wid == 0) {
        float mm = (lane < 4) ? sred[lane] : -3.4e38f;
        #pragma unroll
        for (int o = 2; o > 0; o >>= 1)
            mm = fmaxf(mm, __shfl_xor_sync(0xffffffffu, mm, o));
        if (lane == 0) sbc[0] = mm;
    }
    __syncthreads();
    const float lmax  = sbc[0];
    const float L     = 1.4426950408889634f;
    const float negmL = -lmax * L;

    // ---------- Phase B: e (kept in regs) + weighted value accumulation ----------
    float e_[4];
    float csum = 0.0f;
    ull cv[8];
    #pragma unroll
    for (int i = 0; i < 8; i++) cv[i] = 0ull;

    #pragma unroll
    for (int j = 0; j < 4; j++) {
        const int t = base + tid + j * K1_NTH;
        const float e = ex2f_(fmaf(s[j], L, negmL));
        e_[j] = e;
        csum += e;
        const ull ee = pack2(e, e);
        const ulonglong2* vp =
            reinterpret_cast<const ulonglong2*>(value + ((size_t)b * NT + t) * 16);
        #pragma unroll
        for (int i = 0; i < 4; i++) {
            ulonglong2 vv = vp[i];
            pfma(cv[2*i],   ee, vv.x);
            pfma(cv[2*i+1], ee, vv.y);
        }
    }

    float cvf[16];
    #pragma unroll
    for (int i = 0; i < 8; i++) {
        float2 u = unpack2(cv[i]);
        cvf[2*i] = u.x; cvf[2*i+1] = u.y;
    }

    // ---------- Deterministic 17-value reduction over 4 warps ----------
    #pragma unroll
    for (int o = 16; o > 0; o >>= 1) {
        csum += __shfl_xor_sync(0xffffffffu, csum, o);
        #pragma unroll
        for (int i = 0; i < 16; i++)
            cvf[i] += __shfl_xor_sync(0xffffffffu, cvf[i], o);
    }
    if (lane == 0) {
        sred[wid * 17] = csum;
        #pragma unroll
        for (int i = 0; i < 16; i++) sred[wid * 17 + 1 + i] = cvf[i];
    }
    __syncthreads();
    if (tid < 17) {
        float a = sred[tid];
        #pragma unroll
        for (int w = 1; w < 4; w++) a += sred[w * 17 + tid];
        g_scratch[cta * 18 + 1 + tid] = a;      // sum, ctx[16]
    }
    if (tid == 17) g_scratch[cta * 18] = lmax;
    __syncthreads();   // all scratch writes done before the release-add

    // ---------- Cross-CTA combine: arrive + spin (all 1024 CTAs co-resident) ----------
    if (tid == 0) {
        red_release_add(&g_cnt1[b], 1);
        while (ld_acquire(&g_cnt1[b]) < NCHUNK) __nanosleep(32);
    }
    __syncthreads();

    // All 8 partials visible; compute combine factors (one thread, broadcast)
    if (tid == 0) {
        const float* gs = g_scratch + b * (NCHUNK * 18);
        float gmax = gs[0];
        #pragma unroll
        for (int c = 1; c < NCHUNK; c++) gmax = fmaxf(gmax, gs[c * 18]);
        float cc[NCHUNK];
        float total = 0.0f;
        #pragma unroll
        for (int c = 0; c < NCHUNK; c++) {
            cc[c] = ex2f_((gs[c * 18] - gmax) * L);
            total = fmaf(gs[c * 18 + 1], cc[c], total);
        }
        const float inv = rcpf_(total);
        #pragma unroll
        for (int c = 0; c < NCHUNK; c++) sfac[c] = cc[c] * inv;
    }
    __syncthreads();

    // chunk 0 writes context
    if (chunk == 0 && tid < 16) {
        const float* gs = g_scratch + b * (NCHUNK * 18);
        float acc = 0.0f;
        #pragma unroll
        for (int c = 0; c < NCHUNK; c++)
            acc = fmaf(gs[c * 18 + 2 + tid], sfac[c], acc);
        out_ctx[b * 16 + tid] = acc;
    }

    // write normalized attn straight from registers (single store)
    const float sc = sfac[chunk];
    #pragma unroll
    for (int j = 0; j < 4; j++)
        out_attn[(size_t)b * NT + base + tid + j * K1_NTH] = e_[j] * sc;

    // ---------- Counter reset for graph replay (last CTA of batch) ----------
    __syncthreads();
    if (tid == 0) {
        if (atomicAdd(&g_cnt2[b], 1) == NCHUNK - 1) {
            g_cnt1[b] = 0;
            __threadfence();
            g_cnt2[b] = 0;
        }
    }
}

extern "C" void kernel_launch(void* const* d_in, const int* in_sizes, int n_in,
                              void* d_out, int out_size) {
    const float* query = (const float*)d_in[0];
    const float* key   = (const float*)d_in[1];
    const float* value = (const float*)d_in[2];
    const float* W1    = (const float*)d_in[3];
    const float* W2    = (const float*)d_in[4];
    const float* bias  = (const float*)d_in[5];
    const float* v_w   = (const float*)d_in[6];
    const float* v_b   = (const float*)d_in[7];

    float* out_ctx  = (float*)d_out;            // [B,1,16]
    float* out_attn = (float*)d_out + NB * 16;  // [B,T]

    attn_fused<<<NB * NCHUNK, K1_NTH>>>(query, key, value, W1, W2,
                                        bias, v_w, v_b, out_ctx, out_attn);
}

// round 10
// speedup vs baseline: 1.1167x; 1.0446x over previous
#include <cuda_runtime.h>
#include <cstdint>

typedef unsigned long long ull;

#define NB 128
#define NT 4096
#define K1_NTH 128
#define NCHUNK 8            // CTAs per batch (grid 1024 <= 148*8 resident slots)
#define TOKC 512            // tokens per CTA

__device__ float g_scratch[NB * NCHUNK * 18];   // [cta][lmax, sum, ctx16]
__device__ int   g_cnt1[NB];
__device__ int   g_cnt2[NB];

__device__ __forceinline__ float ex2f_(float x) {
    float y; asm("ex2.approx.f32 %0, %1;" : "=f"(y) : "f"(x)); return y;
}
__device__ __forceinline__ float rcpf_(float x) {
    float y; asm("rcp.approx.f32 %0, %1;" : "=f"(y) : "f"(x)); return y;
}
__device__ __forceinline__ float tanhf_(float x) {
    float y; asm("tanh.approx.f32 %0, %1;" : "=f"(y) : "f"(x)); return y;
}
__device__ __forceinline__ void pfma(ull& d, ull a, ull b) {
    asm("fma.rn.f32x2 %0, %1, %2, %0;" : "+l"(d) : "l"(a), "l"(b));
}
__device__ __forceinline__ ull pack2(float a, float b) {
    ull p; asm("mov.b64 %0, {%1, %2};" : "=l"(p) : "f"(a), "f"(b)); return p;
}
__device__ __forceinline__ float2 unpack2(ull p) {
    float2 r; asm("mov.b64 {%0, %1}, %2;" : "=f"(r.x), "=f"(r.y) : "l"(p)); return r;
}
__device__ __forceinline__ void red_release_add(int* p, int v) {
    asm volatile("red.release.gpu.global.add.s32 [%0], %1;" :: "l"(p), "r"(v) : "memory");
}
__device__ __forceinline__ int ld_acquire(const int* p) {
    int v; asm volatile("ld.acquire.gpu.global.s32 %0, [%1];" : "=r"(v) : "l"(p) : "memory");
    return v;
}
__device__ __forceinline__ uint32_t s2u(const void* p) {
    uint32_t a;
    asm("{ .reg .u64 t; cvta.to.shared.u64 t, %1; cvt.u32.u64 %0, t; }"
        : "=r"(a) : "l"(p));
    return a;
}
__device__ __forceinline__ void cp16(uint32_t dst, const void* g) {
    asm volatile("cp.async.cg.shared.global [%0], [%1], 16;" :: "r"(dst), "l"(g));
}
__device__ __forceinline__ void cpcommit() {
    asm volatile("cp.async.commit_group;");
}
__device__ __forceinline__ void cpwait0() {
    asm volatile("cp.async.wait_group 0;");
}

// swizzled offset of (token, quarter) inside a 64-token x 64B tile buffer
__device__ __forceinline__ uint32_t qoff(int t, int q) {
    return (uint32_t)(t * 64 + ((q ^ ((t >> 1) & 3)) * 16));
}

// stage one 64-token tile (4KB) into this warp's buffer, coalesced
__device__ __forceinline__ void stage_tile(uint32_t sw, const float* gsrc, int lane) {
    #pragma unroll
    for (int k = 0; k < 8; k++) {
        const int c = lane + k * 32;          // 16B chunk id, 0..255
        cp16(sw + qoff(c >> 2, c & 3), gsrc + (size_t)c * 4);
    }
    cpcommit();
}

// read the 2 tokens (lane, lane+32) of the tile into 16 ulls
__device__ __forceinline__ void read_pair(const char* buf, int lane, ull* ka, ull* kb) {
    #pragma unroll
    for (int q = 0; q < 4; q++) {
        ulonglong2 va = *reinterpret_cast<const ulonglong2*>(buf + qoff(lane, q));
        ka[2*q] = va.x; ka[2*q+1] = va.y;
        ulonglong2 vb_ = *reinterpret_cast<const ulonglong2*>(buf + qoff(lane + 32, q));
        kb[2*q] = vb_.x; kb[2*q+1] = vb_.y;
    }
}

__global__ void __launch_bounds__(K1_NTH, 8)
attn_fused(const float* __restrict__ query,   // [B,1,16]
           const float* __restrict__ key,     // [B,T,16]
           const float* __restrict__ value,   // [B,T,16]
           const float* __restrict__ W1,      // [32,16]
           const float* __restrict__ W2,      // [32,16]
           const float* __restrict__ bias,    // scalar
           const float* __restrict__ v_w,     // [1,32]
           const float* __restrict__ v_b,     // [1]
           float* __restrict__ out_ctx,       // [B,16]
           float* __restrict__ out_attn)      // [B,T]
{
    const int cta   = blockIdx.x;
    const int b     = cta >> 3;
    const int chunk = cta & 7;
    const int base  = chunk * TOKC;
    const int tid   = threadIdx.x;
    const int lane  = tid & 31;
    const int wid   = tid >> 5;

    __shared__ __align__(16) char swz[4][4096];   // per-warp staging buffers
    __shared__ ull        sW2p[32 * 8];
    __shared__ ulonglong2 scv[32];
    __shared__ float      sred[4 * 17];
    __shared__ float      sbc[1];
    __shared__ float      sfac[NCHUNK];

    const uint32_t sw   = s2u(swz[wid]);
    const char*    bufc = swz[wid];

    // warp tile bases (64 tokens per warp per pass)
    const int tile0 = base + wid * 64;          // pass 0
    const int tile1 = base + wid * 64 + 256;    // pass 1
    const float* krow = key   + (size_t)b * NT * 16;
    const float* vrow = value + (size_t)b * NT * 16;

    // G1: key tile 0 — issue immediately
    stage_tile(sw, krow + (size_t)tile0 * 16, lane);

    // weight staging + q projection
    {
        float4 wr = reinterpret_cast<const float4*>(W2)[tid];
        sW2p[tid * 2 + 0] = pack2(wr.x, wr.y);
        sW2p[tid * 2 + 1] = pack2(wr.z, wr.w);
    }
    if (tid < 32) {
        const int w = tid;
        float acc = *bias;
        #pragma unroll
        for (int d = 0; d < 16; d++)
            acc = fmaf(query[b * 16 + d], W1[w * 16 + d], acc);
        scv[w].x = pack2(acc, 0.0f);
        scv[w].y = pack2(v_w[w], 0.0f);
    }
    __syncthreads();

    const float vb = *v_b;

    // ---------- Phase A: 2 passes, 2 tokens per thread per pass ----------
    float s[4];
    #pragma unroll
    for (int jp = 0; jp < 2; jp++) {
        cpwait0();
        __syncwarp();
        ull ka[8], kb[8];
        read_pair(bufc, lane, ka, kb);
        __syncwarp();        // all lanes consumed buffer before refill

        if (jp == 0)
            stage_tile(sw, krow + (size_t)tile1 * 16, lane);   // G2: key tile 1
        else
            stage_tile(sw, vrow + (size_t)tile0 * 16, lane);   // G3: value tile A

        float a0 = vb, a1 = vb;
        #pragma unroll 4
        for (int w = 0; w < 32; w++) {
            const ulonglong2 cc = scv[w];
            ull acc0 = cc.x;
            ull acc1 = cc.x;
            const float vw = unpack2(cc.y).x;
            const ulonglong2* wr =
                reinterpret_cast<const ulonglong2*>(&sW2p[w * 8]);
            ulonglong2 wv = wr[0];
            pfma(acc0, ka[0], wv.x); pfma(acc1, kb[0], wv.x);
            pfma(acc0, ka[1], wv.y); pfma(acc1, kb[1], wv.y);
            wv = wr[1];
            pfma(acc0, ka[2], wv.x); pfma(acc1, kb[2], wv.x);
            pfma(acc0, ka[3], wv.y); pfma(acc1, kb[3], wv.y);
            wv = wr[2];
            pfma(acc0, ka[4], wv.x); pfma(acc1, kb[4], wv.x);
            pfma(acc0, ka[5], wv.y); pfma(acc1, kb[5], wv.y);
            wv = wr[3];
            pfma(acc0, ka[6], wv.x); pfma(acc1, kb[6], wv.x);
            pfma(acc0, ka[7], wv.y); pfma(acc1, kb[7], wv.y);

            const float2 h0 = unpack2(acc0);
            const float2 h1 = unpack2(acc1);
            const float t0h = tanhf_(h0.x + h0.y);
            const float t1h = tanhf_(h1.x + h1.y);
            a0 = fmaf(vw, t0h, a0);
            a1 = fmaf(vw, t1h, a1);
        }
        s[2 * jp + 0] = a0;   // token tileN + lane
        s[2 * jp + 1] = a1;   // token tileN + lane + 32
    }

    // ---------- CTA-local max (4 warps) ----------
    float m = fmaxf(fmaxf(s[0], s[1]), fmaxf(s[2], s[3]));
    #pragma unroll
    for (int o = 16; o > 0; o >>= 1)
        m = fmaxf(m, __shfl_xor_sync(0xffffffffu, m, o));
    if (lane == 0) sred[wid] = m;
    __syncthreads();
    if (wid == 0) {
        float mm = (lane < 4) ? sred[lane] : -3.4e38f;
        #pragma unroll
        for (int o = 2; o > 0; o >>= 1)
            mm = fmaxf(mm, __shfl_xor_sync(0xffffffffu, mm, o));
        if (lane == 0) sbc[0] = mm;
    }
    __syncthreads();
    const float lmax  = sbc[0];
    const float L     = 1.4426950408889634f;
    const float negmL = -lmax * L;

    // ---------- Phase B ----------
    float e_[4];
    float csum = 0.0f;
    ull cv[8];
    #pragma unroll
    for (int i = 0; i < 8; i++) cv[i] = 0ull;

    // value tile A (tokens tile0+lane, tile0+lane+32) -> e_[0], e_[1]
    {
        cpwait0();
        __syncwarp();
        ull va[8], vbr[8];
        read_pair(bufc, lane, va, vbr);
        __syncwarp();
        stage_tile(sw, vrow + (size_t)tile1 * 16, lane);       // G4: value tile B

        const float e0 = ex2f_(fmaf(s[0], L, negmL));
        const float e1 = ex2f_(fmaf(s[1], L, negmL));
        e_[0] = e0; e_[1] = e1;
        csum += e0 + e1;
        const ull ee0 = pack2(e0, e0);
        const ull ee1 = pack2(e1, e1);
        #pragma unroll
        for (int i = 0; i < 8; i++) {
            pfma(cv[i], ee0, va[i]);
            pfma(cv[i], ee1, vbr[i]);
        }
    }
    // value tile B (tokens tile1+lane, tile1+lane+32) -> e_[2], e_[3]
    {
        cpwait0();
        __syncwarp();
        ull va[8], vbr[8];
        read_pair(bufc, lane, va, vbr);

        const float e2 = ex2f_(fmaf(s[2], L, negmL));
        const float e3 = ex2f_(fmaf(s[3], L, negmL));
        e_[2] = e2; e_[3] = e3;
        csum += e2 + e3;
        const ull ee2 = pack2(e2, e2);
        const ull ee3 = pack2(e3, e3);
        #pragma unroll
        for (int i = 0; i < 8; i++) {
            pfma(cv[i], ee2, va[i]);
            pfma(cv[i], ee3, vbr[i]);
        }
    }

    float cvf[16];
    #pragma unroll
    for (int i = 0; i < 8; i++) {
        float2 u = unpack2(cv[i]);
        cvf[2*i] = u.x; cvf[2*i+1] = u.y;
    }

    // ---------- Deterministic 17-value reduction over 4 warps ----------
    #pragma unroll
    for (int o = 16; o > 0; o >>= 1) {
        csum += __shfl_xor_sync(0xffffffffu, csum, o);
        #pragma unroll
        for (int i = 0; i < 16; i++)
            cvf[i] += __shfl_xor_sync(0xffffffffu, cvf[i], o);
    }
    if (lane == 0) {
        sred[wid * 17] = csum;
        #pragma unroll
        for (int i = 0; i < 16; i++) sred[wid * 17 + 1 + i] = cvf[i];
    }
    __syncthreads();
    if (tid < 17) {
        float a = sred[tid];
        #pragma unroll
        for (int w = 1; w < 4; w++) a += sred[w * 17 + tid];
        g_scratch[cta * 18 + 1 + tid] = a;
    }
    if (tid == 17) g_scratch[cta * 18] = lmax;
    __syncthreads();

    // ---------- Cross-CTA combine: arrive + spin ----------
    if (tid == 0) {
        red_release_add(&g_cnt1[b], 1);
        while (ld_acquire(&g_cnt1[b]) < NCHUNK) __nanosleep(32);
    }
    __syncthreads();

    if (tid == 0) {
        const float* gs = g_scratch + b * (NCHUNK * 18);
        float gmax = gs[0];
        #pragma unroll
        for (int c = 1; c < NCHUNK; c++) gmax = fmaxf(gmax, gs[c * 18]);
        float cc[NCHUNK];
        float total = 0.0f;
        #pragma unroll
        for (int c = 0; c < NCHUNK; c++) {
            cc[c] = ex2f_((gs[c * 18] - gmax) * L);
            total = fmaf(gs[c * 18 + 1], cc[c], total);
        }
        const float inv = rcpf_(total);
        #pragma unroll
        for (int c = 0; c < NCHUNK; c++) sfac[c] = cc[c] * inv;
    }
    __syncthreads();

    if (chunk == 0 && tid < 16) {
        const float* gs = g_scratch + b * (NCHUNK * 18);
        float acc = 0.0f;
        #pragma unroll
        for (int c = 0; c < NCHUNK; c++)
            acc = fmaf(gs[c * 18 + 2 + tid], sfac[c], acc);
        out_ctx[b * 16 + tid] = acc;
    }

    // write normalized attn (token layout: tileN + lane, tileN + lane + 32)
    const float sc = sfac[chunk];
    float* ao = out_attn + (size_t)b * NT;
    ao[tile0 + lane]      = e_[0] * sc;
    ao[tile0 + lane + 32] = e_[1] * sc;
    ao[tile1 + lane]      = e_[2] * sc;
    ao[tile1 + lane + 32] = e_[3] * sc;

    // ---------- Counter reset for graph replay ----------
    __syncthreads();
    if (tid == 0) {
        if (atomicAdd(&g_cnt2[b], 1) == NCHUNK - 1) {
            g_cnt1[b] = 0;
            __threadfence();
            g_cnt2[b] = 0;
        }
    }
}

extern "C" void kernel_launch(void* const* d_in, const int* in_sizes, int n_in,
                              void* d_out, int out_size) {
    const float* query = (const float*)d_in[0];
    const float* key   = (const float*)d_in[1];
    const float* value = (const float*)d_in[2];
    const float* W1    = (const float*)d_in[3];
    const float* W2    = (const float*)d_in[4];
    const float* bias  = (const float*)d_in[5];
    const float* v_w   = (const float*)d_in[6];
    const float* v_b   = (const float*)d_in[7];

    float* out_ctx  = (float*)d_out;            // [B,1,16]
    float* out_attn = (float*)d_out + NB * 16;  // [B,T]

    static bool configured = false;
    if (!configured) {
        cudaFuncSetAttribute(attn_fused,
                             cudaFuncAttributePreferredSharedMemoryCarveout, 100);
        configured = true;
    }

    attn_fused<<<NB * NCHUNK, K1_NTH>>>(query, key, value, W1, W2,
                                        bias, v_w, v_b, out_ctx, out_attn);
}

// round 11
// speedup vs baseline: 1.2465x; 1.1162x over previous
#include <cuda_runtime.h>
#include <cstdint>

typedef unsigned long long ull;

#define NB 128
#define NT 4096
#define K1_NTH 128
#define NCHUNK 8            // CTAs per batch (grid 1024 <= 148*8 resident slots)
#define TOKC 512            // tokens per CTA

__device__ float g_scratch[NB * NCHUNK * 18];   // [cta][lmax, sum, ctx16]
__device__ int   g_cnt1[NB];
__device__ int   g_cnt2[NB];

__constant__ ull   cW2p[32 * 8];   // W2 rows as packed float pairs (direct copy)
__constant__ float cvw[32];        // v_w

__device__ __forceinline__ float ex2f_(float x) {
    float y; asm("ex2.approx.f32 %0, %1;" : "=f"(y) : "f"(x)); return y;
}
__device__ __forceinline__ float rcpf_(float x) {
    float y; asm("rcp.approx.f32 %0, %1;" : "=f"(y) : "f"(x)); return y;
}
__device__ __forceinline__ float tanhf_(float x) {
    float y; asm("tanh.approx.f32 %0, %1;" : "=f"(y) : "f"(x)); return y;
}
__device__ __forceinline__ void pfma(ull& d, ull a, ull b) {
    asm("fma.rn.f32x2 %0, %1, %2, %0;" : "+l"(d) : "l"(a), "l"(b));
}
__device__ __forceinline__ ull pack2(float a, float b) {
    ull p; asm("mov.b64 %0, {%1, %2};" : "=l"(p) : "f"(a), "f"(b)); return p;
}
__device__ __forceinline__ float2 unpack2(ull p) {
    float2 r; asm("mov.b64 {%0, %1}, %2;" : "=f"(r.x), "=f"(r.y) : "l"(p)); return r;
}
__device__ __forceinline__ void red_release_add(int* p, int v) {
    asm volatile("red.release.gpu.global.add.s32 [%0], %1;" :: "l"(p), "r"(v) : "memory");
}
__device__ __forceinline__ int ld_acquire(const int* p) {
    int v; asm volatile("ld.acquire.gpu.global.s32 %0, [%1];" : "=r"(v) : "l"(p) : "memory");
    return v;
}
__device__ __forceinline__ uint32_t s2u(const void* p) {
    uint32_t a;
    asm("{ .reg .u64 t; cvta.to.shared.u64 t, %1; cvt.u32.u64 %0, t; }"
        : "=r"(a) : "l"(p));
    return a;
}
__device__ __forceinline__ void cp16(uint32_t dst, const void* g) {
    asm volatile("cp.async.cg.shared.global [%0], [%1], 16;" :: "r"(dst), "l"(g));
}
__device__ __forceinline__ void cpcommit() {
    asm volatile("cp.async.commit_group;");
}
__device__ __forceinline__ void cpwait0() {
    asm volatile("cp.async.wait_group 0;");
}

// swizzled offset of (token, quarter) inside a 64-token x 64B tile buffer
__device__ __forceinline__ uint32_t qoff(int t, int q) {
    return (uint32_t)(t * 64 + ((q ^ ((t >> 1) & 3)) * 16));
}

__device__ __forceinline__ void stage_tile(uint32_t sw, const float* gsrc, int lane) {
    #pragma unroll
    for (int k = 0; k < 8; k++) {
        const int c = lane + k * 32;
        cp16(sw + qoff(c >> 2, c & 3), gsrc + (size_t)c * 4);
    }
    cpcommit();
}

__device__ __forceinline__ void read_pair(const char* buf, int lane, ull* ka, ull* kb) {
    #pragma unroll
    for (int q = 0; q < 4; q++) {
        ulonglong2 va = *reinterpret_cast<const ulonglong2*>(buf + qoff(lane, q));
        ka[2*q] = va.x; ka[2*q+1] = va.y;
        ulonglong2 vb_ = *reinterpret_cast<const ulonglong2*>(buf + qoff(lane + 32, q));
        kb[2*q] = vb_.x; kb[2*q+1] = vb_.y;
    }
}

__global__ void __launch_bounds__(K1_NTH, 8)
attn_fused(const float* __restrict__ query,   // [B,1,16]
           const float* __restrict__ key,     // [B,T,16]
           const float* __restrict__ value,   // [B,T,16]
           const float* __restrict__ W1,      // [32,16]
           const float* __restrict__ bias,    // scalar
           const float* __restrict__ v_b,     // [1]
           float* __restrict__ out_ctx,       // [B,16]
           float* __restrict__ out_attn)      // [B,T]
{
    const int cta   = blockIdx.x;
    const int b     = cta >> 3;
    const int chunk = cta & 7;
    const int base  = chunk * TOKC;
    const int tid   = threadIdx.x;
    const int lane  = tid & 31;
    const int wid   = tid >> 5;

    __shared__ __align__(16) char swz[4][4096];   // per-warp staging buffers
    __shared__ ull   sqp[32];        // (qproj_w + bias, 0) packed
    __shared__ float sred[4 * 17];
    __shared__ float sbc[1];
    __shared__ float sfac[NCHUNK];

    const uint32_t sw   = s2u(swz[wid]);
    const char*    bufc = swz[wid];

    const int tile0 = base + wid * 64;          // pass 0
    const int tile1 = base + wid * 64 + 256;    // pass 1
    const float* krow = key   + (size_t)b * NT * 16;
    const float* vrow = value + (size_t)b * NT * 16;

    // G1: key tile 0 — issue immediately
    stage_tile(sw, krow + (size_t)tile0 * 16, lane);

    // q projection (W2/v_w now come from __constant__)
    if (tid < 32) {
        const int w = tid;
        float acc = *bias;
        #pragma unroll
        for (int d = 0; d < 16; d++)
            acc = fmaf(query[b * 16 + d], W1[w * 16 + d], acc);
        sqp[w] = pack2(acc, 0.0f);
    }
    __syncthreads();

    const float vb = *v_b;

    // ---------- Phase A: 2 passes, 2 tokens per thread per pass ----------
    float s[4];
    #pragma unroll
    for (int jp = 0; jp < 2; jp++) {
        cpwait0();
        __syncwarp();
        ull ka[8], kb[8];
        read_pair(bufc, lane, ka, kb);
        __syncwarp();

        if (jp == 0)
            stage_tile(sw, krow + (size_t)tile1 * 16, lane);   // G2: key tile 1
        else
            stage_tile(sw, vrow + (size_t)tile0 * 16, lane);   // G3: value tile A

        float a0 = vb, a1 = vb;
        #pragma unroll 4
        for (int w = 0; w < 32; w++) {
            ull acc0 = sqp[w];      // single LDS.64 broadcast per w
            ull acc1 = acc0;
            const ull* wr = &cW2p[w * 8];      // const-port loads
            pfma(acc0, ka[0], wr[0]); pfma(acc1, kb[0], wr[0]);
            pfma(acc0, ka[1], wr[1]); pfma(acc1, kb[1], wr[1]);
            pfma(acc0, ka[2], wr[2]); pfma(acc1, kb[2], wr[2]);
            pfma(acc0, ka[3], wr[3]); pfma(acc1, kb[3], wr[3]);
            pfma(acc0, ka[4], wr[4]); pfma(acc1, kb[4], wr[4]);
            pfma(acc0, ka[5], wr[5]); pfma(acc1, kb[5], wr[5]);
            pfma(acc0, ka[6], wr[6]); pfma(acc1, kb[6], wr[6]);
            pfma(acc0, ka[7], wr[7]); pfma(acc1, kb[7], wr[7]);

            const float2 h0 = unpack2(acc0);
            const float2 h1 = unpack2(acc1);
            const float t0h = tanhf_(h0.x + h0.y);
            const float t1h = tanhf_(h1.x + h1.y);
            const float vw = cvw[w];
            a0 = fmaf(vw, t0h, a0);
            a1 = fmaf(vw, t1h, a1);
        }
        s[2 * jp + 0] = a0;   // token tileN + lane
        s[2 * jp + 1] = a1;   // token tileN + lane + 32
    }

    // ---------- CTA-local max (4 warps) ----------
    float m = fmaxf(fmaxf(s[0], s[1]), fmaxf(s[2], s[3]));
    #pragma unroll
    for (int o = 16; o > 0; o >>= 1)
        m = fmaxf(m, __shfl_xor_sync(0xffffffffu, m, o));
    if (lane == 0) sred[wid] = m;
    __syncthreads();
    if (wid == 0) {
        float mm = (lane < 4) ? sred[lane] : -3.4e38f;
        #pragma unroll
        for (int o = 2; o > 0; o >>= 1)
            mm = fmaxf(mm, __shfl_xor_sync(0xffffffffu, mm, o));
        if (lane == 0) sbc[0] = mm;
    }
    __syncthreads();
    const float lmax  = sbc[0];
    const float L     = 1.4426950408889634f;
    const float negmL = -lmax * L;

    // ---------- Phase B ----------
    float e_[4];
    float csum = 0.0f;
    ull cv[8];
    #pragma unroll
    for (int i = 0; i < 8; i++) cv[i] = 0ull;

    {   // value tile A -> e_[0], e_[1]
        cpwait0();
        __syncwarp();
        ull va[8], vbr[8];
        read_pair(bufc, lane, va, vbr);
        __syncwarp();
        stage_tile(sw, vrow + (size_t)tile1 * 16, lane);       // G4: value tile B

        const float e0 = ex2f_(fmaf(s[0], L, negmL));
        const float e1 = ex2f_(fmaf(s[1], L, negmL));
        e_[0] = e0; e_[1] = e1;
        csum += e0 + e1;
        const ull ee0 = pack2(e0, e0);
        const ull ee1 = pack2(e1, e1);
        #pragma unroll
        for (int i = 0; i < 8; i++) {
            pfma(cv[i], ee0, va[i]);
            pfma(cv[i], ee1, vbr[i]);
        }
    }
    {   // value tile B -> e_[2], e_[3]
        cpwait0();
        __syncwarp();
        ull va[8], vbr[8];
        read_pair(bufc, lane, va, vbr);

        const float e2 = ex2f_(fmaf(s[2], L, negmL));
        const float e3 = ex2f_(fmaf(s[3], L, negmL));
        e_[2] = e2; e_[3] = e3;
        csum += e2 + e3;
        const ull ee2 = pack2(e2, e2);
        const ull ee3 = pack2(e3, e3);
        #pragma unroll
        for (int i = 0; i < 8; i++) {
            pfma(cv[i], ee2, va[i]);
            pfma(cv[i], ee3, vbr[i]);
        }
    }

    float cvf[16];
    #pragma unroll
    for (int i = 0; i < 8; i++) {
        float2 u = unpack2(cv[i]);
        cvf[2*i] = u.x; cvf[2*i+1] = u.y;
    }

    // ---------- Deterministic 17-value reduction over 4 warps ----------
    #pragma unroll
    for (int o = 16; o > 0; o >>= 1) {
        csum += __shfl_xor_sync(0xffffffffu, csum, o);
        #pragma unroll
        for (int i = 0; i < 16; i++)
            cvf[i] += __shfl_xor_sync(0xffffffffu, cvf[i], o);
    }
    if (lane == 0) {
        sred[wid * 17] = csum;
        #pragma unroll
        for (int i = 0; i < 16; i++) sred[wid * 17 + 1 + i] = cvf[i];
    }
    __syncthreads();
    if (tid < 17) {
        float a = sred[tid];
        #pragma unroll
        for (int w = 1; w < 4; w++) a += sred[w * 17 + tid];
        g_scratch[cta * 18 + 1 + tid] = a;
    }
    if (tid == 17) g_scratch[cta * 18] = lmax;
    __syncthreads();

    // ---------- Cross-CTA combine: arrive + spin ----------
    if (tid == 0) {
        red_release_add(&g_cnt1[b], 1);
        while (ld_acquire(&g_cnt1[b]) < NCHUNK) __nanosleep(32);
    }
    __syncthreads();

    if (tid == 0) {
        const float* gs = g_scratch + b * (NCHUNK * 18);
        float gmax = gs[0];
        #pragma unroll
        for (int c = 1; c < NCHUNK; c++) gmax = fmaxf(gmax, gs[c * 18]);
        float cc[NCHUNK];
        float total = 0.0f;
        #pragma unroll
        for (int c = 0; c < NCHUNK; c++) {
            cc[c] = ex2f_((gs[c * 18] - gmax) * L);
            total = fmaf(gs[c * 18 + 1], cc[c], total);
        }
        const float inv = rcpf_(total);
        #pragma unroll
        for (int c = 0; c < NCHUNK; c++) sfac[c] = cc[c] * inv;
    }
    __syncthreads();

    if (chunk == 0 && tid < 16) {
        const float* gs = g_scratch + b * (NCHUNK * 18);
        float acc = 0.0f;
        #pragma unroll
        for (int c = 0; c < NCHUNK; c++)
            acc = fmaf(gs[c * 18 + 2 + tid], sfac[c], acc);
        out_ctx[b * 16 + tid] = acc;
    }

    const float sc = sfac[chunk];
    float* ao = out_attn + (size_t)b * NT;
    ao[tile0 + lane]      = e_[0] * sc;
    ao[tile0 + lane + 32] = e_[1] * sc;
    ao[tile1 + lane]      = e_[2] * sc;
    ao[tile1 + lane + 32] = e_[3] * sc;

    // ---------- Counter reset for graph replay ----------
    __syncthreads();
    if (tid == 0) {
        if (atomicAdd(&g_cnt2[b], 1) == NCHUNK - 1) {
            g_cnt1[b] = 0;
            __threadfence();
            g_cnt2[b] = 0;
        }
    }
}

extern "C" void kernel_launch(void* const* d_in, const int* in_sizes, int n_in,
                              void* d_out, int out_size) {
    const float* query = (const float*)d_in[0];
    const float* key   = (const float*)d_in[1];
    const float* value = (const float*)d_in[2];
    const float* W1    = (const float*)d_in[3];
    const float* W2    = (const float*)d_in[4];
    const float* bias  = (const float*)d_in[5];
    const float* v_w   = (const float*)d_in[6];
    const float* v_b   = (const float*)d_in[7];

    float* out_ctx  = (float*)d_out;            // [B,1,16]
    float* out_attn = (float*)d_out + NB * 16;  // [B,T]

    // Stage batch-independent weights into __constant__ (D2D memcpy nodes,
    // graph-capturable, re-executed deterministically on every replay).
    cudaMemcpyToSymbolAsync(cW2p, W2, 32 * 16 * sizeof(float), 0,
                            cudaMemcpyDeviceToDevice);
    cudaMemcpyToSymbolAsync(cvw, v_w, 32 * sizeof(float), 0,
                            cudaMemcpyDeviceToDevice);

    attn_fused<<<NB * NCHUNK, K1_NTH>>>(query, key, value, W1,
                                        bias, v_b, out_ctx, out_attn);
}

// round 12
// speedup vs baseline: 1.2594x; 1.0103x over previous
#include <cuda_runtime.h>
#include <cstdint>

typedef unsigned long long ull;

#define NB 128
#define NT 4096
#define K1_NTH 128
#define NCHUNK 8            // CTAs per batch (grid 1024 <= 148*8 resident slots)
#define TOKC 512            // tokens per CTA

__device__ float g_scratch[NB * NCHUNK * 18];   // [cta][sum, ctx16]
__device__ int   g_cnt1[NB];
__device__ int   g_cnt2[NB];

__constant__ ull   cW2p[32 * 8];   // W2 rows as packed float pairs
__constant__ float cvw[32];        // v_w

__device__ __forceinline__ float ex2f_(float x) {
    float y; asm("ex2.approx.f32 %0, %1;" : "=f"(y) : "f"(x)); return y;
}
__device__ __forceinline__ float rcpf_(float x) {
    float y; asm("rcp.approx.f32 %0, %1;" : "=f"(y) : "f"(x)); return y;
}
__device__ __forceinline__ float tanhf_(float x) {
    float y; asm("tanh.approx.f32 %0, %1;" : "=f"(y) : "f"(x)); return y;
}
__device__ __forceinline__ void pfma(ull& d, ull a, ull b) {
    asm("fma.rn.f32x2 %0, %1, %2, %0;" : "+l"(d) : "l"(a), "l"(b));
}
__device__ __forceinline__ ull pack2(float a, float b) {
    ull p; asm("mov.b64 %0, {%1, %2};" : "=l"(p) : "f"(a), "f"(b)); return p;
}
__device__ __forceinline__ float2 unpack2(ull p) {
    float2 r; asm("mov.b64 {%0, %1}, %2;" : "=f"(r.x), "=f"(r.y) : "l"(p)); return r;
}
__device__ __forceinline__ void red_release_add(int* p, int v) {
    asm volatile("red.release.gpu.global.add.s32 [%0], %1;" :: "l"(p), "r"(v) : "memory");
}
__device__ __forceinline__ int ld_acquire(const int* p) {
    int v; asm volatile("ld.acquire.gpu.global.s32 %0, [%1];" : "=r"(v) : "l"(p) : "memory");
    return v;
}
__device__ __forceinline__ uint32_t s2u(const void* p) {
    uint32_t a;
    asm("{ .reg .u64 t; cvta.to.shared.u64 t, %1; cvt.u32.u64 %0, t; }"
        : "=r"(a) : "l"(p));
    return a;
}
__device__ __forceinline__ void cp16(uint32_t dst, const void* g) {
    asm volatile("cp.async.cg.shared.global [%0], [%1], 16;" :: "r"(dst), "l"(g));
}
__device__ __forceinline__ void cpcommit() {
    asm volatile("cp.async.commit_group;");
}
__device__ __forceinline__ void cpwait0() {
    asm volatile("cp.async.wait_group 0;");
}

// swizzled offset of (token, quarter) inside a 64-token x 64B tile buffer
__device__ __forceinline__ uint32_t qoff(int t, int q) {
    return (uint32_t)(t * 64 + ((q ^ ((t >> 1) & 3)) * 16));
}

__device__ __forceinline__ void stage_tile(uint32_t sw, const float* gsrc, int lane) {
    #pragma unroll
    for (int k = 0; k < 8; k++) {
        const int c = lane + k * 32;
        cp16(sw + qoff(c >> 2, c & 3), gsrc + (size_t)c * 4);
    }
    cpcommit();
}

__device__ __forceinline__ void read_pair(const char* buf, int lane, ull* ka, ull* kb) {
    #pragma unroll
    for (int q = 0; q < 4; q++) {
        ulonglong2 va = *reinterpret_cast<const ulonglong2*>(buf + qoff(lane, q));
        ka[2*q] = va.x; ka[2*q+1] = va.y;
        ulonglong2 vb_ = *reinterpret_cast<const ulonglong2*>(buf + qoff(lane + 32, q));
        kb[2*q] = vb_.x; kb[2*q+1] = vb_.y;
    }
}

__global__ void __launch_bounds__(K1_NTH, 8)
attn_fused(const float* __restrict__ query,   // [B,1,16]
           const float* __restrict__ key,     // [B,T,16]
           const float* __restrict__ value,   // [B,T,16]
           const float* __restrict__ W1,      // [32,16]
           const float* __restrict__ bias,    // scalar
           const float* __restrict__ v_b,     // [1]
           float* __restrict__ out_ctx,       // [B,16]
           float* __restrict__ out_attn)      // [B,T]
{
    const int cta   = blockIdx.x;
    const int b     = cta >> 3;
    const int chunk = cta & 7;
    const int base  = chunk * TOKC;
    const int tid   = threadIdx.x;
    const int lane  = tid & 31;
    const int wid   = tid >> 5;

    __shared__ __align__(16) char swz[4][4096];   // per-warp staging buffers
    __shared__ ull   sqp[32];        // (qproj_w + bias, 0) packed
    __shared__ float sred[4 * 17];
    __shared__ float sbc[1];         // broadcast: global inv

    const uint32_t sw   = s2u(swz[wid]);
    const char*    bufc = swz[wid];

    const int tile0 = base + wid * 64;          // pass 0 tokens
    const int tile1 = base + wid * 64 + 256;    // pass 1 tokens
    const float* krow = key   + (size_t)b * NT * 16;
    const float* vrow = value + (size_t)b * NT * 16;

    // G1: key tile 0 — issue immediately
    stage_tile(sw, krow + (size_t)tile0 * 16, lane);

    // q projection (W2/v_w come from __constant__)
    if (tid < 32) {
        const int w = tid;
        float acc = *bias;
        #pragma unroll
        for (int d = 0; d < 16; d++)
            acc = fmaf(query[b * 16 + d], W1[w * 16 + d], acc);
        sqp[w] = pack2(acc, 0.0f);
    }
    __syncthreads();

    const float vb = *v_b;
    const float L  = 1.4426950408889634f;

    // ---------- Scores + inline exp (no max pass: |score| <= |v_b|+sum|v_w|) ----
    float e_[4];
    float csum = 0.0f;

    #pragma unroll
    for (int jp = 0; jp < 2; jp++) {
        cpwait0();
        __syncwarp();
        ull ka[8], kb[8];
        read_pair(bufc, lane, ka, kb);
        __syncwarp();

        if (jp == 0)
            stage_tile(sw, krow + (size_t)tile1 * 16, lane);   // G2: key tile 1
        else
            stage_tile(sw, vrow + (size_t)tile0 * 16, lane);   // G3: value tile A

        float a0 = vb, a1 = vb;
        #pragma unroll 4
        for (int w = 0; w < 32; w++) {
            ull acc0 = sqp[w];
            ull acc1 = acc0;
            const ull* wr = &cW2p[w * 8];
            pfma(acc0, ka[0], wr[0]); pfma(acc1, kb[0], wr[0]);
            pfma(acc0, ka[1], wr[1]); pfma(acc1, kb[1], wr[1]);
            pfma(acc0, ka[2], wr[2]); pfma(acc1, kb[2], wr[2]);
            pfma(acc0, ka[3], wr[3]); pfma(acc1, kb[3], wr[3]);
            pfma(acc0, ka[4], wr[4]); pfma(acc1, kb[4], wr[4]);
            pfma(acc0, ka[5], wr[5]); pfma(acc1, kb[5], wr[5]);
            pfma(acc0, ka[6], wr[6]); pfma(acc1, kb[6], wr[6]);
            pfma(acc0, ka[7], wr[7]); pfma(acc1, kb[7], wr[7]);

            const float2 h0 = unpack2(acc0);
            const float2 h1 = unpack2(acc1);
            const float t0h = tanhf_(h0.x + h0.y);
            const float t1h = tanhf_(h1.x + h1.y);
            const float vw = cvw[w];
            a0 = fmaf(vw, t0h, a0);
            a1 = fmaf(vw, t1h, a1);
        }
        const float e0 = ex2f_(a0 * L);    // exp(score), unnormalized — safe
        const float e1 = ex2f_(a1 * L);
        e_[2 * jp + 0] = e0;
        e_[2 * jp + 1] = e1;
        csum += e0 + e1;
    }

    // ---------- Value accumulation (two tiles, pipelined) ----------
    ull cv[8];
    #pragma unroll
    for (int i = 0; i < 8; i++) cv[i] = 0ull;

    {   // value tile A (tokens tile0+lane, tile0+lane+32)
        cpwait0();
        __syncwarp();
        ull va[8], vbr[8];
        read_pair(bufc, lane, va, vbr);
        __syncwarp();
        stage_tile(sw, vrow + (size_t)tile1 * 16, lane);       // G4: value tile B

        const ull ee0 = pack2(e_[0], e_[0]);
        const ull ee1 = pack2(e_[1], e_[1]);
        #pragma unroll
        for (int i = 0; i < 8; i++) {
            pfma(cv[i], ee0, va[i]);
            pfma(cv[i], ee1, vbr[i]);
        }
    }
    {   // value tile B (tokens tile1+lane, tile1+lane+32)
        cpwait0();
        __syncwarp();
        ull va[8], vbr[8];
        read_pair(bufc, lane, va, vbr);

        const ull ee2 = pack2(e_[2], e_[2]);
        const ull ee3 = pack2(e_[3], e_[3]);
        #pragma unroll
        for (int i = 0; i < 8; i++) {
            pfma(cv[i], ee2, va[i]);
            pfma(cv[i], ee3, vbr[i]);
        }
    }

    float cvf[16];
    #pragma unroll
    for (int i = 0; i < 8; i++) {
        float2 u = unpack2(cv[i]);
        cvf[2*i] = u.x; cvf[2*i+1] = u.y;
    }

    // ---------- Deterministic 17-value reduction over 4 warps ----------
    #pragma unroll
    for (int o = 16; o > 0; o >>= 1) {
        csum += __shfl_xor_sync(0xffffffffu, csum, o);
        #pragma unroll
        for (int i = 0; i < 16; i++)
            cvf[i] += __shfl_xor_sync(0xffffffffu, cvf[i], o);
    }
    if (lane == 0) {
        sred[wid * 17] = csum;
        #pragma unroll
        for (int i = 0; i < 16; i++) sred[wid * 17 + 1 + i] = cvf[i];
    }
    __syncthreads();
    if (tid < 17) {
        float a = sred[tid];
        #pragma unroll
        for (int w = 1; w < 4; w++) a += sred[w * 17 + tid];
        g_scratch[cta * 18 + tid] = a;       // [0]=sum, [1..16]=ctx
    }
    __syncthreads();

    // ---------- Cross-CTA combine: arrive + spin (sum only, no factors) ------
    if (tid == 0) {
        red_release_add(&g_cnt1[b], 1);
        while (ld_acquire(&g_cnt1[b]) < NCHUNK) __nanosleep(32);
    }
    __syncthreads();

    if (tid == 0) {
        const float* gs = g_scratch + b * (NCHUNK * 18);
        float total = 0.0f;
        #pragma unroll
        for (int c = 0; c < NCHUNK; c++) total += gs[c * 18];
        sbc[0] = rcpf_(total);
    }
    __syncthreads();
    const float inv = sbc[0];

    if (chunk == 0 && tid < 16) {
        const float* gs = g_scratch + b * (NCHUNK * 18);
        float acc = 0.0f;
        #pragma unroll
        for (int c = 0; c < NCHUNK; c++) acc += gs[c * 18 + 1 + tid];
        out_ctx[b * 16 + tid] = acc * inv;
    }

    float* ao = out_attn + (size_t)b * NT;
    ao[tile0 + lane]      = e_[0] * inv;
    ao[tile0 + lane + 32] = e_[1] * inv;
    ao[tile1 + lane]      = e_[2] * inv;
    ao[tile1 + lane + 32] = e_[3] * inv;

    // ---------- Counter reset for graph replay ----------
    __syncthreads();
    if (tid == 0) {
        if (atomicAdd(&g_cnt2[b], 1) == NCHUNK - 1) {
            g_cnt1[b] = 0;
            __threadfence();
            g_cnt2[b] = 0;
        }
    }
}

extern "C" void kernel_launch(void* const* d_in, const int* in_sizes, int n_in,
                              void* d_out, int out_size) {
    const float* query = (const float*)d_in[0];
    const float* key   = (const float*)d_in[1];
    const float* value = (const float*)d_in[2];
    const float* W1    = (const float*)d_in[3];
    const float* W2    = (const float*)d_in[4];
    const float* bias  = (const float*)d_in[5];
    const float* v_w   = (const float*)d_in[6];
    const float* v_b   = (const float*)d_in[7];

    float* out_ctx  = (float*)d_out;            // [B,1,16]
    float* out_attn = (float*)d_out + NB * 16;  // [B,T]

    cudaMemcpyToSymbolAsync(cW2p, W2, 32 * 16 * sizeof(float), 0,
                            cudaMemcpyDeviceToDevice);
    cudaMemcpyToSymbolAsync(cvw, v_w, 32 * sizeof(float), 0,
                            cudaMemcpyDeviceToDevice);

    attn_fused<<<NB * NCHUNK, K1_NTH>>>(query, key, value, W1,
                                        bias, v_b, out_ctx, out_attn);
}